// round 1
// baseline (speedup 1.0000x reference)
#include <cuda_runtime.h>
#include <math.h>

#define TSTEPS 128
#define FEAT   512
#define HID    1024
#define NBLK   128
#define NTH    256

// Scratch (no allocations allowed): per-step hidden states + per-step arrival counters.
__device__ float    g_h[TSTEPS * HID];
__device__ unsigned g_ready[TSTEPS];

__global__ void pg_init() {
    if (threadIdx.x < TSTEPS) g_ready[threadIdx.x] = 0u;
}

__device__ __forceinline__ unsigned ld_acq(const unsigned* p) {
    unsigned v;
    asm volatile("ld.global.acquire.gpu.u32 %0, [%1];" : "=r"(v) : "l"(p) : "memory");
    return v;
}

__global__ void __launch_bounds__(NTH, 1) pg_rnn(
    const float* __restrict__ x,   // (1, T, F)
    const float* __restrict__ h0,  // (H,)
    const float* __restrict__ Ws,  // (T, F+H, H)
    const float* __restrict__ bs,  // (T, H)
    const float* __restrict__ Wo,  // (H, 2)
    const float* __restrict__ bo,  // (2,)
    float* __restrict__ out)       // [actors(2), h_final(H)]
{
    const int tid  = threadIdx.x;
    const int g    = tid >> 3;     // 0..31 : row group
    const int jj   = tid & 7;      // 0..7  : column within block slice
    const int lane = tid & 31;
    const int warp = tid >> 5;
    const int j    = (blockIdx.x << 3) + jj;

    __shared__ float s_red[64];

    for (int t = 0; t < TSTEPS; ++t) {
        const float* Wt = Ws + (size_t)t * (FEAT + HID) * HID;
        const float* xt = x + t * FEAT;

        float a0 = 0.f, a1 = 0.f, a2 = 0.f, a3 = 0.f;

        // ---- x-part: no dependency, streams while previous step finishes ----
        {
            const float* wp = Wt + (size_t)g * HID + j;
#pragma unroll
            for (int k = 0; k < 16; ++k) {
                float w  = wp[(size_t)k * 32 * HID];
                float xv = xt[g + 32 * k];
                if      ((k & 3) == 0) a0 = fmaf(xv, w, a0);
                else if ((k & 3) == 1) a1 = fmaf(xv, w, a1);
                else if ((k & 3) == 2) a2 = fmaf(xv, w, a2);
                else                   a3 = fmaf(xv, w, a3);
            }
        }

        // ---- issue h-part weight loads into registers BEFORE the spin ----
        float wh[32];
        {
            const float* wp = Wt + (size_t)(FEAT + g) * HID + j;
#pragma unroll
            for (int k = 0; k < 32; ++k)
                wh[k] = wp[(size_t)k * 32 * HID];
        }

        // ---- acquire previous hidden state ----
        const float* hprev = (t == 0) ? h0 : (g_h + (size_t)(t - 1) * HID);
        if (t > 0) {
            if (tid == 0) {
                while (ld_acq(&g_ready[t - 1]) != (unsigned)NBLK) { }
            }
            __syncthreads();
            __threadfence();
        }

        // ---- h-part FMAs (weights already in flight / in regs) ----
#pragma unroll
        for (int k = 0; k < 32; ++k) {
            float hv = hprev[g + 32 * k];
            if      ((k & 3) == 0) a0 = fmaf(hv, wh[k], a0);
            else if ((k & 3) == 1) a1 = fmaf(hv, wh[k], a1);
            else if ((k & 3) == 2) a2 = fmaf(hv, wh[k], a2);
            else                   a3 = fmaf(hv, wh[k], a3);
        }
        float acc = (a0 + a1) + (a2 + a3);

        // reduce over g: within warp lanes differ by 8,16,24
        acc += __shfl_xor_sync(0xffffffffu, acc, 8);
        acc += __shfl_xor_sync(0xffffffffu, acc, 16);
        if (lane < 8) s_red[warp * 8 + lane] = acc;
        __syncthreads();

        if (tid < 8) {
            float s = 0.f;
#pragma unroll
            for (int w = 0; w < 8; ++w) s += s_red[w * 8 + tid];
            const int jc = (blockIdx.x << 3) + tid;
            float hv = tanhf(s + bs[t * HID + jc]);
            g_h[(size_t)t * HID + jc] = hv;
            if (t == TSTEPS - 1) out[2 + jc] = hv;
        }

        // release: stores visible before the counter bump
        __threadfence();
        __syncthreads();
        if (tid == 0) atomicAdd(&g_ready[t], 1u);
    }

    // ---- final actor head (block 0 only) ----
    if (blockIdx.x == 0) {
        if (tid == 0) {
            while (ld_acq(&g_ready[TSTEPS - 1]) != (unsigned)NBLK) { }
        }
        __syncthreads();
        __threadfence();

        const float* hf = g_h + (size_t)(TSTEPS - 1) * HID;
        float r0 = 0.f, r1 = 0.f;
        for (int i = tid; i < HID; i += NTH) {
            float hv = hf[i];
            r0 = fmaf(hv, Wo[2 * i + 0], r0);
            r1 = fmaf(hv, Wo[2 * i + 1], r1);
        }
#pragma unroll
        for (int o = 16; o > 0; o >>= 1) {
            r0 += __shfl_xor_sync(0xffffffffu, r0, o);
            r1 += __shfl_xor_sync(0xffffffffu, r1, o);
        }
        __shared__ float sa[16];
        if (lane == 0) { sa[warp] = r0; sa[8 + warp] = r1; }
        __syncthreads();
        if (tid == 0) {
            float s0 = 0.f, s1 = 0.f;
#pragma unroll
            for (int w = 0; w < 8; ++w) { s0 += sa[w]; s1 += sa[8 + w]; }
            out[0] = s0 + bo[0];
            out[1] = s1 + bo[1];
        }
    }
}

extern "C" void kernel_launch(void* const* d_in, const int* in_sizes, int n_in,
                              void* d_out, int out_size) {
    const float* x  = (const float*)d_in[0];
    const float* h0 = (const float*)d_in[1];
    const float* Ws = (const float*)d_in[2];
    const float* bs = (const float*)d_in[3];
    const float* Wo = (const float*)d_in[4];
    const float* bo = (const float*)d_in[5];
    float* out = (float*)d_out;

    pg_init<<<1, 128>>>();
    pg_rnn<<<NBLK, NTH>>>(x, h0, Ws, bs, Wo, bo, out);
}